// round 1
// baseline (speedup 1.0000x reference)
#include <cuda_runtime.h>
#include <math.h>

// Problem constants (fixed shapes for this problem)
#define NATOMS 50000
#define NB     10000
#define NE     320000
#define TABN   4096
#define DMAX   8.0f

typedef unsigned long long ull;

// ------------------------- scratch (device globals; no allocs allowed) ----
__device__ float g_Wab[256 * 128];            // [Wa;Wb] folded dihedral weights
__device__ float g_S[NB * 256];               // [fi+fl | fj+fk]
__device__ float g_rbf[NB * 128];             // rb_feats
__device__ float g_q[NB * 128];               // q per bond
__device__ float g_rbpos[NB * 3];
__device__ float g_katom[NATOMS * 128];       // atom part of k (incl. bk)
__device__ float g_vatom[NATOMS * 128];       // atom part of v (incl. bv)
__device__ float g_tab[TABN * 256];           // per-row: hk[128] | hv[128]
__device__ float g_msg[NB * 128];
__device__ float g_o1[NB * 128];
__device__ float g_h[NB * 128];
__device__ int   g_cnt[NB];
__device__ int   g_off[NB + 1];
__device__ int   g_cur[NB];
__device__ int   g_eidx[NE];

// ------------------------- f32x2 packed-FMA helpers -----------------------
__device__ __forceinline__ ull pack2(float x, float y) {
    ull r;
    asm("mov.b64 %0, {%1, %2};" : "=l"(r) : "f"(x), "f"(y));
    return r;
}
__device__ __forceinline__ void unpack2(ull v, float& lo, float& hi) {
    asm("mov.b64 {%0, %1}, %2;" : "=f"(lo), "=f"(hi) : "l"(v));
}
__device__ __forceinline__ void fma2(ull& d, ull a, ull b) {
    asm("fma.rn.f32x2 %0, %1, %2, %0;" : "+l"(d) : "l"(a), "l"(b));
}

// ------------------------- small prep kernels -----------------------------
// Wab: rows 0..127 = W0+W3, rows 128..255 = W1+W2 (W_dih is [512,128] row-major)
__global__ void prep_wab(const float* __restrict__ Wd) {
    int idx = blockIdx.x * blockDim.x + threadIdx.x;   // 0..32767
    if (idx >= 256 * 128) return;
    int r = idx >> 7;
    int other = (r < 128) ? (idx + 384 * 128) : (idx + 128 * 128);
    g_Wab[idx] = Wd[idx] + Wd[other];
}

// dist-embedding table: row r holds hk(d_r)[128] | hv(d_r)[128],
// h(d) = dist_embed(d) @ W*_bot  (rows 128..159 of Wk/Wv)
__global__ __launch_bounds__(128) void build_table(const float* __restrict__ Wk,
                                                   const float* __restrict__ Wv) {
    __shared__ float wk[32][128];
    __shared__ float wv[32][128];
    __shared__ float ev[32];
    int tid = threadIdx.x;
    for (int idx = tid; idx < 32 * 128; idx += 128) {
        int r = idx >> 7, c = idx & 127;
        wk[r][c] = Wk[(128 + r) * 128 + c];
        wv[r][c] = Wv[(128 + r) * 128 + c];
    }
    __syncthreads();
    const float delta = 5.0f / 31.0f;
    const float coeff = -0.5f / (delta * delta);
    const float step  = DMAX / (float)(TABN - 1);
    for (int rr = 0; rr < 16; rr++) {
        int row = blockIdx.x * 16 + rr;
        float d = row * step;
        if (tid < 32) {
            float t = d - tid * delta;
            ev[tid] = expf(coeff * t * t);
        }
        __syncthreads();
        float hk = 0.f, hv = 0.f;
#pragma unroll
        for (int j = 0; j < 32; j++) {
            hk += ev[j] * wk[j][tid];
            hv += ev[j] * wv[j][tid];
        }
        g_tab[(size_t)row * 256 + tid]       = hk;
        g_tab[(size_t)row * 256 + 128 + tid] = hv;
        __syncthreads();
    }
}

__global__ void zero_cnt() {
    int b = blockIdx.x * blockDim.x + threadIdx.x;
    if (b < NB) g_cnt[b] = 0;
}

__global__ void hist_kernel(const int* __restrict__ etgt) {
    int e = blockIdx.x * blockDim.x + threadIdx.x;
    if (e < NE) atomicAdd(&g_cnt[etgt[e]], 1);
}

__global__ __launch_bounds__(1024) void scan_kernel() {
    __shared__ int sm[1024];
    int t = threadIdx.x;
    const int CH = 10;                    // 1024*10 >= NB
    int base = t * CH;
    int loc[CH];
    int tot = 0;
#pragma unroll
    for (int i = 0; i < CH; i++) {
        int v = (base + i < NB) ? g_cnt[base + i] : 0;
        loc[i] = tot;
        tot += v;
    }
    sm[t] = tot;
    __syncthreads();
    for (int off = 1; off < 1024; off <<= 1) {
        int v = (t >= off) ? sm[t - off] : 0;
        __syncthreads();
        sm[t] += v;
        __syncthreads();
    }
    int excl = sm[t] - tot;
#pragma unroll
    for (int i = 0; i < CH; i++) {
        if (base + i < NB) {
            int o = excl + loc[i];
            g_off[base + i] = o;
            g_cur[base + i] = o;
        }
    }
    if (t == 1023) g_off[NB] = sm[1023];
}

__global__ void scatter_kernel(const int* __restrict__ etgt) {
    int e = blockIdx.x * blockDim.x + threadIdx.x;
    if (e < NE) {
        int p = atomicAdd(&g_cur[etgt[e]], 1);
        g_eidx[p] = e;
    }
}

// deterministic order within each bond (atomics above are unordered)
__global__ void sort_lists() {
    int b = blockIdx.x * blockDim.x + threadIdx.x;
    if (b >= NB) return;
    int s = g_off[b], e = g_off[b + 1];
    for (int i = s + 1; i < e; i++) {
        int key = g_eidx[i];
        int j = i - 1;
        while (j >= s && g_eidx[j] > key) {
            g_eidx[j + 1] = g_eidx[j];
            j--;
        }
        g_eidx[j + 1] = key;
    }
}

// S[b] = [fi+fl | fj+fk]
__global__ void gather_S(const float* __restrict__ feats, const int* __restrict__ tt) {
    int idx = blockIdx.x * blockDim.x + threadIdx.x;
    if (idx >= NB * 128) return;
    int b = idx >> 7, c = idx & 127;
    int ai = tt[b * 4 + 0], aj = tt[b * 4 + 1], ak = tt[b * 4 + 2], al = tt[b * 4 + 3];
    g_S[(size_t)b * 256 + c]       = feats[(size_t)ai * 128 + c] + feats[(size_t)al * 128 + c];
    g_S[(size_t)b * 256 + 128 + c] = feats[(size_t)aj * 128 + c] + feats[(size_t)ak * 128 + c];
}

__global__ void rbpos_kernel(const int* __restrict__ rbi, const float* __restrict__ coords) {
    int b = blockIdx.x * blockDim.x + threadIdx.x;
    if (b >= NB) return;
    int a0 = rbi[b], a1 = rbi[NB + b];
#pragma unroll
    for (int i = 0; i < 3; i++)
        g_rbpos[b * 3 + i] = 0.5f * (coords[(size_t)a0 * 3 + i] + coords[(size_t)a1 * 3 + i]);
}

// ------------------------- GEMM: C[M,128] = A[M,K] @ W[K,128] + s*bias ----
// 64x128 block tile, 256 threads, 4x8 micro-tile, f32x2 packed accumulators.
template <int K, bool GELU>
__global__ __launch_bounds__(256) void gemm_kernel(const float* __restrict__ A,
                                                   const float* __restrict__ W,
                                                   const float* __restrict__ bias,
                                                   float bscale,
                                                   float* __restrict__ C, int M) {
    __shared__ float As[32][65];    // transposed A tile (k-major)
    __shared__ float Ws[32][128];
    const int tid = threadIdx.x;
    const int tx = tid & 15;        // col group: 8 cols
    const int ty = tid >> 4;        // row group: 4 rows
    const int m0 = blockIdx.x * 64;

    ull acc[4][4];
#pragma unroll
    for (int r = 0; r < 4; r++)
#pragma unroll
        for (int j = 0; j < 4; j++) acc[r][j] = 0ull;

    for (int kc = 0; kc < K; kc += 32) {
#pragma unroll
        for (int it = 0; it < 2; it++) {
            int lin = tid + 256 * it;          // 0..511 float4 slots
            int row = lin >> 3;                // 64 rows
            int c4 = lin & 7;                  // 8 float4 per 32-col row
            float4 v = make_float4(0.f, 0.f, 0.f, 0.f);
            int gr = m0 + row;
            if (gr < M) v = *(const float4*)(A + (size_t)gr * K + kc + c4 * 4);
            As[c4 * 4 + 0][row] = v.x;
            As[c4 * 4 + 1][row] = v.y;
            As[c4 * 4 + 2][row] = v.z;
            As[c4 * 4 + 3][row] = v.w;
        }
#pragma unroll
        for (int it = 0; it < 4; it++) {
            int lin = tid + 256 * it;          // 0..1023 float4 slots
            int row = lin >> 5;                // 32 rows
            int c4 = lin & 31;                 // 32 float4 per 128-col row
            *(float4*)&Ws[row][c4 * 4] =
                *(const float4*)(W + (size_t)(kc + row) * 128 + c4 * 4);
        }
        __syncthreads();
#pragma unroll
        for (int k = 0; k < 32; k++) {
            float a0 = As[k][ty * 4 + 0], a1 = As[k][ty * 4 + 1];
            float a2 = As[k][ty * 4 + 2], a3 = As[k][ty * 4 + 3];
            ull pa0 = pack2(a0, a0), pa1 = pack2(a1, a1);
            ull pa2 = pack2(a2, a2), pa3 = pack2(a3, a3);
            const ull* wp = (const ull*)&Ws[k][tx * 8];
            ull w0 = wp[0], w1 = wp[1], w2 = wp[2], w3 = wp[3];
            fma2(acc[0][0], pa0, w0); fma2(acc[0][1], pa0, w1);
            fma2(acc[0][2], pa0, w2); fma2(acc[0][3], pa0, w3);
            fma2(acc[1][0], pa1, w0); fma2(acc[1][1], pa1, w1);
            fma2(acc[1][2], pa1, w2); fma2(acc[1][3], pa1, w3);
            fma2(acc[2][0], pa2, w0); fma2(acc[2][1], pa2, w1);
            fma2(acc[2][2], pa2, w2); fma2(acc[2][3], pa2, w3);
            fma2(acc[3][0], pa3, w0); fma2(acc[3][1], pa3, w1);
            fma2(acc[3][2], pa3, w2); fma2(acc[3][3], pa3, w3);
        }
        __syncthreads();
    }

    float bb[8];
#pragma unroll
    for (int j = 0; j < 8; j++) bb[j] = bscale * bias[tx * 8 + j];
#pragma unroll
    for (int r = 0; r < 4; r++) {
        int gr = m0 + ty * 4 + r;
        if (gr >= M) continue;
#pragma unroll
        for (int j = 0; j < 4; j++) {
            float lo, hi;
            unpack2(acc[r][j], lo, hi);
            lo += bb[j * 2];
            hi += bb[j * 2 + 1];
            if (GELU) {
                lo = 0.5f * lo * (1.f + erff(lo * 0.70710678118654752f));
                hi = 0.5f * hi * (1.f + erff(hi * 0.70710678118654752f));
            }
            *(float2*)(C + (size_t)gr * 128 + tx * 8 + j * 2) = make_float2(lo, hi);
        }
    }
}

// ------------------------- attention: block per bond, online softmax ------
__global__ __launch_bounds__(128) void attn_kernel(const int* __restrict__ edge_src,
                                                   const float* __restrict__ coords) {
    const int b = blockIdx.x;
    const int c = threadIdx.x;                 // channel 0..127; head = c/16
    const float qc = g_q[(size_t)b * 128 + c];
    const float rx = g_rbpos[b * 3 + 0];
    const float ry = g_rbpos[b * 3 + 1];
    const float rz = g_rbpos[b * 3 + 2];
    const int s0 = g_off[b], s1 = g_off[b + 1];
    const float INVSTEP = (float)(TABN - 1) / DMAX;

    float m = -1e30f, ssum = 0.f, acc = 0.f;
    for (int i = s0; i < s1; i++) {
        int e = g_eidx[i];
        int src = edge_src[e];
        float dx = coords[(size_t)src * 3 + 0] - rx;
        float dy = coords[(size_t)src * 3 + 1] - ry;
        float dz = coords[(size_t)src * 3 + 2] - rz;
        float dist = sqrtf(dx * dx + dy * dy + dz * dz);
        float u = fminf(dist * INVSTEP, (float)(TABN - 1) - 1e-3f);
        int i0 = (int)u;
        float f = u - (float)i0;
        const float* t0 = &g_tab[(size_t)i0 * 256];
        float hk = t0[c] + f * (t0[256 + c] - t0[c]);
        float hv = t0[128 + c] + f * (t0[384 + c] - t0[128 + c]);
        float kv = g_katom[(size_t)src * 128 + c] + hk;
        float vv = g_vatom[(size_t)src * 128 + c] + hv;

        float part = qc * kv;                  // reduce within 16-lane head group
        part += __shfl_xor_sync(0xffffffffu, part, 8);
        part += __shfl_xor_sync(0xffffffffu, part, 4);
        part += __shfl_xor_sync(0xffffffffu, part, 2);
        part += __shfl_xor_sync(0xffffffffu, part, 1);
        float l = part * 0.25f;                // 1/sqrt(HEAD_DIM)

        float mn = fmaxf(m, l);
        float sc = __expf(m - mn);
        float p = __expf(l - mn);
        ssum = ssum * sc + p;
        acc = acc * sc + p * vv;
        m = mn;
    }
    g_msg[(size_t)b * 128 + c] = acc / (ssum + 1e-16f);
}

// ------------------------- final tiny GEMM: y = h @ Wt2 + bt2 -------------
__global__ void t2_kernel(const float* __restrict__ Wt2, const float* __restrict__ bt2,
                          float* __restrict__ out) {
    int gt = blockIdx.x * blockDim.x + threadIdx.x;
    int warp = gt >> 5;
    int lane = gt & 31;
    if (warp >= NB) return;
    float a0 = 0.f, a1 = 0.f;
#pragma unroll
    for (int k = lane; k < 128; k += 32) {
        float h = g_h[(size_t)warp * 128 + k];
        a0 += h * Wt2[k * 2 + 0];
        a1 += h * Wt2[k * 2 + 1];
    }
#pragma unroll
    for (int o = 16; o; o >>= 1) {
        a0 += __shfl_xor_sync(0xffffffffu, a0, o);
        a1 += __shfl_xor_sync(0xffffffffu, a1, o);
    }
    if (lane == 0) {
        out[warp * 2 + 0] = a0 + bt2[0];
        out[warp * 2 + 1] = a1 + bt2[1];
    }
}

// ------------------------- launch -----------------------------------------
extern "C" void kernel_launch(void* const* d_in, const int* in_sizes, int n_in,
                              void* d_out, int out_size) {
    const float* atom_feats = (const float*)d_in[0];
    const float* coords     = (const float*)d_in[1];
    const int*   rbi        = (const int*)d_in[2];
    const int*   etgt       = (const int*)d_in[3];
    const int*   esrc       = (const int*)d_in[4];
    const int*   tt         = (const int*)d_in[5];
    const float* W_dih      = (const float*)d_in[6];
    const float* b_dih      = (const float*)d_in[7];
    const float* Wq         = (const float*)d_in[8];
    const float* bq         = (const float*)d_in[9];
    const float* Wk         = (const float*)d_in[10];
    const float* bk         = (const float*)d_in[11];
    const float* Wv         = (const float*)d_in[12];
    const float* bv         = (const float*)d_in[13];
    const float* Wout       = (const float*)d_in[14];
    const float* bout       = (const float*)d_in[15];
    const float* Wt1        = (const float*)d_in[16];
    const float* bt1        = (const float*)d_in[17];
    const float* Wt2        = (const float*)d_in[18];
    const float* bt2        = (const float*)d_in[19];
    float* out = (float*)d_out;

    // device-global scratch addresses (symbol lookup only; no allocation)
    float *pWab, *pS, *pRbf, *pQ, *pKat, *pVat, *pMsg, *pO1, *pH;
    cudaGetSymbolAddress((void**)&pWab, g_Wab);
    cudaGetSymbolAddress((void**)&pS, g_S);
    cudaGetSymbolAddress((void**)&pRbf, g_rbf);
    cudaGetSymbolAddress((void**)&pQ, g_q);
    cudaGetSymbolAddress((void**)&pKat, g_katom);
    cudaGetSymbolAddress((void**)&pVat, g_vatom);
    cudaGetSymbolAddress((void**)&pMsg, g_msg);
    cudaGetSymbolAddress((void**)&pO1, g_o1);
    cudaGetSymbolAddress((void**)&pH, g_h);

    // prep
    prep_wab<<<(256 * 128 + 255) / 256, 256>>>(W_dih);
    build_table<<<TABN / 16, 128>>>(Wk, Wv);

    // edge counting sort by target bond (deterministic after per-bond sort)
    zero_cnt<<<(NB + 255) / 256, 256>>>();
    hist_kernel<<<(NE + 255) / 256, 256>>>(etgt);
    scan_kernel<<<1, 1024>>>();
    scatter_kernel<<<(NE + 255) / 256, 256>>>(etgt);
    sort_lists<<<(NB + 127) / 128, 128>>>();

    // bond-side features
    gather_S<<<(NB * 128 + 255) / 256, 256>>>(atom_feats, tt);
    rbpos_kernel<<<(NB + 127) / 128, 128>>>(rbi, coords);
    gemm_kernel<256, false><<<(NB + 63) / 64, 256>>>(pS, pWab, b_dih, 2.0f, pRbf, NB);
    gemm_kernel<128, false><<<(NB + 63) / 64, 256>>>(pRbf, Wq, bq, 1.0f, pQ, NB);

    // atom-side k/v (first 128 rows of Wk/Wv; dist part comes from the table)
    gemm_kernel<128, false><<<(NATOMS + 63) / 64, 256>>>(atom_feats, Wk, bk, 1.0f, pKat, NATOMS);
    gemm_kernel<128, false><<<(NATOMS + 63) / 64, 256>>>(atom_feats, Wv, bv, 1.0f, pVat, NATOMS);

    // fused per-bond attention (logits + softmax + weighted value sum)
    attn_kernel<<<NB, 128>>>(esrc, coords);

    // output MLP
    gemm_kernel<128, false><<<(NB + 63) / 64, 256>>>(pMsg, Wout, bout, 1.0f, pO1, NB);
    gemm_kernel<128, true><<<(NB + 63) / 64, 256>>>(pO1, Wt1, bt1, 1.0f, pH, NB);
    t2_kernel<<<(NB * 32 + 127) / 128, 128>>>(Wt2, bt2, out);

    (void)in_sizes; (void)n_in; (void)out_size;
}

// round 2
// speedup vs baseline: 1.2076x; 1.2076x over previous
#include <cuda_runtime.h>
#include <math.h>

// Problem constants (fixed shapes for this problem)
#define NATOMS 50000
#define NB     10000
#define NE     320000
#define TABN   4096
#define DMAX   8.0f
#define MAXE   256

typedef unsigned long long ull;

// ------------------------- scratch (device globals; no allocs allowed) ----
__device__ float g_Wab[256 * 128];            // folded dihedral weights
__device__ float g_Wfq[256 * 128];            // Wab @ Wq
__device__ float g_bfq[128];
__device__ float g_Wo1[128 * 128];            // Wout @ Wt1
__device__ float g_bo1[128];
__device__ float g_S[NB * 256];               // [fi+fl | fj+fk]
__device__ float g_q[NB * 128];
__device__ float g_rbpos[NB * 3];
__device__ float g_katom[NATOMS * 128];
__device__ float g_vatom[NATOMS * 128];
__device__ float g_tab[TABN * 256];           // row: hk[128] | hv[128]
__device__ float g_msg[NB * 128];
__device__ float g_h[NB * 128];
__device__ int   g_cnt[NB];
__device__ int   g_off[NB + 1];
__device__ int   g_cur[NB];
__device__ int   g_eidx[NE];

// ------------------------- f32x2 packed-FMA helpers -----------------------
__device__ __forceinline__ ull pack2(float x, float y) {
    ull r;
    asm("mov.b64 %0, {%1, %2};" : "=l"(r) : "f"(x), "f"(y));
    return r;
}
__device__ __forceinline__ void unpack2(ull v, float& lo, float& hi) {
    asm("mov.b64 {%0, %1}, %2;" : "=f"(lo), "=f"(hi) : "l"(v));
}
__device__ __forceinline__ void fma2(ull& d, ull a, ull b) {
    asm("fma.rn.f32x2 %0, %1, %2, %0;" : "+l"(d) : "l"(a), "l"(b));
}

// ------------------------- small prep kernels -----------------------------
// Wab: rows 0..127 = W0+W3, rows 128..255 = W1+W2
__global__ void prep_wab(const float* __restrict__ Wd) {
    int idx = blockIdx.x * blockDim.x + threadIdx.x;
    if (idx >= 256 * 128) return;
    int r = idx >> 7;
    int other = (r < 128) ? (idx + 384 * 128) : (idx + 128 * 128);
    g_Wab[idx] = Wd[idx] + Wd[other];
}

// fused biases: bfq = bq + 2*b_dih@Wq ; bo1 = bt1 + bout@Wt1
__global__ __launch_bounds__(128) void prep_bias(const float* __restrict__ b_dih,
                                                 const float* __restrict__ Wq,
                                                 const float* __restrict__ bq,
                                                 const float* __restrict__ bout,
                                                 const float* __restrict__ Wt1,
                                                 const float* __restrict__ bt1) {
    int c = threadIdx.x;
    float s1 = 0.f, s2 = 0.f;
    for (int k = 0; k < 128; k++) {
        s1 += b_dih[k] * Wq[k * 128 + c];
        s2 += bout[k] * Wt1[k * 128 + c];
    }
    g_bfq[c] = bq[c] + 2.f * s1;
    g_bo1[c] = bt1[c] + s2;
}

// dist-embedding table
__global__ __launch_bounds__(128) void build_table(const float* __restrict__ Wk,
                                                   const float* __restrict__ Wv) {
    __shared__ float wk[32][128];
    __shared__ float wv[32][128];
    __shared__ float ev[32];
    int tid = threadIdx.x;
    for (int idx = tid; idx < 32 * 128; idx += 128) {
        int r = idx >> 7, c = idx & 127;
        wk[r][c] = Wk[(128 + r) * 128 + c];
        wv[r][c] = Wv[(128 + r) * 128 + c];
    }
    __syncthreads();
    const float delta = 5.0f / 31.0f;
    const float coeff = -0.5f / (delta * delta);
    const float step  = DMAX / (float)(TABN - 1);
    for (int rr = 0; rr < 16; rr++) {
        int row = blockIdx.x * 16 + rr;
        float d = row * step;
        if (tid < 32) {
            float t = d - tid * delta;
            ev[tid] = expf(coeff * t * t);
        }
        __syncthreads();
        float hk = 0.f, hv = 0.f;
#pragma unroll
        for (int j = 0; j < 32; j++) {
            hk += ev[j] * wk[j][tid];
            hv += ev[j] * wv[j][tid];
        }
        g_tab[(size_t)row * 256 + tid]       = hk;
        g_tab[(size_t)row * 256 + 128 + tid] = hv;
        __syncthreads();
    }
}

__global__ void zero_cnt() {
    int b = blockIdx.x * blockDim.x + threadIdx.x;
    if (b < NB) g_cnt[b] = 0;
}

__global__ void hist_kernel(const int* __restrict__ etgt) {
    int e = blockIdx.x * blockDim.x + threadIdx.x;
    if (e < NE) atomicAdd(&g_cnt[etgt[e]], 1);
}

__global__ __launch_bounds__(1024) void scan_kernel() {
    __shared__ int sm[1024];
    int t = threadIdx.x;
    const int CH = 10;
    int base = t * CH;
    int loc[CH];
    int tot = 0;
#pragma unroll
    for (int i = 0; i < CH; i++) {
        int v = (base + i < NB) ? g_cnt[base + i] : 0;
        loc[i] = tot;
        tot += v;
    }
    sm[t] = tot;
    __syncthreads();
    for (int off = 1; off < 1024; off <<= 1) {
        int v = (t >= off) ? sm[t - off] : 0;
        __syncthreads();
        sm[t] += v;
        __syncthreads();
    }
    int excl = sm[t] - tot;
#pragma unroll
    for (int i = 0; i < CH; i++) {
        if (base + i < NB) {
            int o = excl + loc[i];
            g_off[base + i] = o;
            g_cur[base + i] = o;
        }
    }
    if (t == 1023) g_off[NB] = sm[1023];
}

__global__ void scatter_kernel(const int* __restrict__ etgt) {
    int e = blockIdx.x * blockDim.x + threadIdx.x;
    if (e < NE) {
        int p = atomicAdd(&g_cur[etgt[e]], 1);
        g_eidx[p] = e;
    }
}

// deterministic order within each bond: warp-per-bond rank sort in shared
__global__ __launch_bounds__(256) void sort_lists() {
    __shared__ int buf[8][MAXE];
    int warp = threadIdx.x >> 5, lane = threadIdx.x & 31;
    int b = blockIdx.x * 8 + warp;
    if (b >= NB) return;
    int s = g_off[b], e = g_off[b + 1];
    int n = e - s;
    if (n <= 1) return;
    if (n <= MAXE) {
        for (int i = lane; i < n; i += 32) buf[warp][i] = g_eidx[s + i];
        __syncwarp();
        for (int i = lane; i < n; i += 32) {
            int v = buf[warp][i];
            int r = 0;
            for (int j = 0; j < n; j++) r += (buf[warp][j] < v);
            g_eidx[s + r] = v;
        }
    } else if (lane == 0) {   // safety fallback (never expected for this data)
        for (int i = s + 1; i < e; i++) {
            int key = g_eidx[i];
            int j = i - 1;
            while (j >= s && g_eidx[j] > key) { g_eidx[j + 1] = g_eidx[j]; j--; }
            g_eidx[j + 1] = key;
        }
    }
}

// S[b] = [fi+fl | fj+fk]
__global__ void gather_S(const float* __restrict__ feats, const int* __restrict__ tt) {
    int idx = blockIdx.x * blockDim.x + threadIdx.x;
    if (idx >= NB * 128) return;
    int b = idx >> 7, c = idx & 127;
    int ai = tt[b * 4 + 0], aj = tt[b * 4 + 1], ak = tt[b * 4 + 2], al = tt[b * 4 + 3];
    g_S[(size_t)b * 256 + c]       = feats[(size_t)ai * 128 + c] + feats[(size_t)al * 128 + c];
    g_S[(size_t)b * 256 + 128 + c] = feats[(size_t)aj * 128 + c] + feats[(size_t)ak * 128 + c];
}

__global__ void rbpos_kernel(const int* __restrict__ rbi, const float* __restrict__ coords) {
    int b = blockIdx.x * blockDim.x + threadIdx.x;
    if (b >= NB) return;
    int a0 = rbi[b], a1 = rbi[NB + b];
#pragma unroll
    for (int i = 0; i < 3; i++)
        g_rbpos[b * 3 + i] = 0.5f * (coords[(size_t)a0 * 3 + i] + coords[(size_t)a1 * 3 + i]);
}

// ------------------------- GEMM: C[M,128] = A[M,K] @ W[K,128] + s*bias ----
template <int K, bool GELU>
__global__ __launch_bounds__(256) void gemm_kernel(const float* __restrict__ A,
                                                   const float* __restrict__ W,
                                                   const float* __restrict__ bias,
                                                   float bscale,
                                                   float* __restrict__ C, int M) {
    __shared__ float As[32][65];
    __shared__ float Ws[32][128];
    const int tid = threadIdx.x;
    const int tx = tid & 15;
    const int ty = tid >> 4;
    const int m0 = blockIdx.x * 64;

    ull acc[4][4];
#pragma unroll
    for (int r = 0; r < 4; r++)
#pragma unroll
        for (int j = 0; j < 4; j++) acc[r][j] = 0ull;

    for (int kc = 0; kc < K; kc += 32) {
#pragma unroll
        for (int it = 0; it < 2; it++) {
            int lin = tid + 256 * it;
            int row = lin >> 3;
            int c4 = lin & 7;
            float4 v = make_float4(0.f, 0.f, 0.f, 0.f);
            int gr = m0 + row;
            if (gr < M) v = *(const float4*)(A + (size_t)gr * K + kc + c4 * 4);
            As[c4 * 4 + 0][row] = v.x;
            As[c4 * 4 + 1][row] = v.y;
            As[c4 * 4 + 2][row] = v.z;
            As[c4 * 4 + 3][row] = v.w;
        }
#pragma unroll
        for (int it = 0; it < 4; it++) {
            int lin = tid + 256 * it;
            int row = lin >> 5;
            int c4 = lin & 31;
            *(float4*)&Ws[row][c4 * 4] =
                *(const float4*)(W + (size_t)(kc + row) * 128 + c4 * 4);
        }
        __syncthreads();
#pragma unroll
        for (int k = 0; k < 32; k++) {
            float a0 = As[k][ty * 4 + 0], a1 = As[k][ty * 4 + 1];
            float a2 = As[k][ty * 4 + 2], a3 = As[k][ty * 4 + 3];
            ull pa0 = pack2(a0, a0), pa1 = pack2(a1, a1);
            ull pa2 = pack2(a2, a2), pa3 = pack2(a3, a3);
            const ull* wp = (const ull*)&Ws[k][tx * 8];
            ull w0 = wp[0], w1 = wp[1], w2 = wp[2], w3 = wp[3];
            fma2(acc[0][0], pa0, w0); fma2(acc[0][1], pa0, w1);
            fma2(acc[0][2], pa0, w2); fma2(acc[0][3], pa0, w3);
            fma2(acc[1][0], pa1, w0); fma2(acc[1][1], pa1, w1);
            fma2(acc[1][2], pa1, w2); fma2(acc[1][3], pa1, w3);
            fma2(acc[2][0], pa2, w0); fma2(acc[2][1], pa2, w1);
            fma2(acc[2][2], pa2, w2); fma2(acc[2][3], pa2, w3);
            fma2(acc[3][0], pa3, w0); fma2(acc[3][1], pa3, w1);
            fma2(acc[3][2], pa3, w2); fma2(acc[3][3], pa3, w3);
        }
        __syncthreads();
    }

    float bb[8];
#pragma unroll
    for (int j = 0; j < 8; j++) bb[j] = bscale * bias[tx * 8 + j];
#pragma unroll
    for (int r = 0; r < 4; r++) {
        int gr = m0 + ty * 4 + r;
        if (gr >= M) continue;
#pragma unroll
        for (int j = 0; j < 4; j++) {
            float lo, hi;
            unpack2(acc[r][j], lo, hi);
            lo += bb[j * 2];
            hi += bb[j * 2 + 1];
            if (GELU) {
                lo = 0.5f * lo * (1.f + erff(lo * 0.70710678118654752f));
                hi = 0.5f * hi * (1.f + erff(hi * 0.70710678118654752f));
            }
            *(float2*)(C + (size_t)gr * 128 + tx * 8 + j * 2) = make_float2(lo, hi);
        }
    }
}

// ---------- dual GEMM (shared A tile): C1 = A@W1+b1 ; C2 = A@W2+b2 (K=128) -
__global__ __launch_bounds__(256) void gemm_dual(const float* __restrict__ A,
                                                 const float* __restrict__ W1,
                                                 const float* __restrict__ b1,
                                                 const float* __restrict__ W2,
                                                 const float* __restrict__ b2,
                                                 float* __restrict__ C1,
                                                 float* __restrict__ C2, int M) {
    __shared__ float As[32][65];
    __shared__ float Ws[2][32][128];
    const int tid = threadIdx.x;
    const int tx = tid & 15;
    const int ty = tid >> 4;
    const int m0 = blockIdx.x * 64;

    ull acc[2][4][4];
#pragma unroll
    for (int p = 0; p < 2; p++)
#pragma unroll
        for (int r = 0; r < 4; r++)
#pragma unroll
            for (int j = 0; j < 4; j++) acc[p][r][j] = 0ull;

    for (int kc = 0; kc < 128; kc += 32) {
#pragma unroll
        for (int it = 0; it < 2; it++) {
            int lin = tid + 256 * it;
            int row = lin >> 3;
            int c4 = lin & 7;
            float4 v = make_float4(0.f, 0.f, 0.f, 0.f);
            int gr = m0 + row;
            if (gr < M) v = *(const float4*)(A + (size_t)gr * 128 + kc + c4 * 4);
            As[c4 * 4 + 0][row] = v.x;
            As[c4 * 4 + 1][row] = v.y;
            As[c4 * 4 + 2][row] = v.z;
            As[c4 * 4 + 3][row] = v.w;
        }
#pragma unroll
        for (int it = 0; it < 4; it++) {
            int lin = tid + 256 * it;
            int row = lin >> 5;
            int c4 = lin & 31;
            *(float4*)&Ws[0][row][c4 * 4] =
                *(const float4*)(W1 + (size_t)(kc + row) * 128 + c4 * 4);
            *(float4*)&Ws[1][row][c4 * 4] =
                *(const float4*)(W2 + (size_t)(kc + row) * 128 + c4 * 4);
        }
        __syncthreads();
#pragma unroll
        for (int k = 0; k < 32; k++) {
            float a0 = As[k][ty * 4 + 0], a1 = As[k][ty * 4 + 1];
            float a2 = As[k][ty * 4 + 2], a3 = As[k][ty * 4 + 3];
            ull pa0 = pack2(a0, a0), pa1 = pack2(a1, a1);
            ull pa2 = pack2(a2, a2), pa3 = pack2(a3, a3);
#pragma unroll
            for (int p = 0; p < 2; p++) {
                const ull* wp = (const ull*)&Ws[p][k][tx * 8];
                ull w0 = wp[0], w1 = wp[1], w2 = wp[2], w3 = wp[3];
                fma2(acc[p][0][0], pa0, w0); fma2(acc[p][0][1], pa0, w1);
                fma2(acc[p][0][2], pa0, w2); fma2(acc[p][0][3], pa0, w3);
                fma2(acc[p][1][0], pa1, w0); fma2(acc[p][1][1], pa1, w1);
                fma2(acc[p][1][2], pa1, w2); fma2(acc[p][1][3], pa1, w3);
                fma2(acc[p][2][0], pa2, w0); fma2(acc[p][2][1], pa2, w1);
                fma2(acc[p][2][2], pa2, w2); fma2(acc[p][2][3], pa2, w3);
                fma2(acc[p][3][0], pa3, w0); fma2(acc[p][3][1], pa3, w1);
                fma2(acc[p][3][2], pa3, w2); fma2(acc[p][3][3], pa3, w3);
            }
        }
        __syncthreads();
    }

#pragma unroll
    for (int p = 0; p < 2; p++) {
        const float* bias = p ? b2 : b1;
        float* C = p ? C2 : C1;
        float bb[8];
#pragma unroll
        for (int j = 0; j < 8; j++) bb[j] = bias[tx * 8 + j];
#pragma unroll
        for (int r = 0; r < 4; r++) {
            int gr = m0 + ty * 4 + r;
            if (gr >= M) continue;
#pragma unroll
            for (int j = 0; j < 4; j++) {
                float lo, hi;
                unpack2(acc[p][r][j], lo, hi);
                *(float2*)(C + (size_t)gr * 128 + tx * 8 + j * 2) =
                    make_float2(lo + bb[j * 2], hi + bb[j * 2 + 1]);
            }
        }
    }
}

// ------------------------- attention: 4 warps split edges, flash merge ----
__global__ __launch_bounds__(128) void attn_kernel(const int* __restrict__ edge_src,
                                                   const float* __restrict__ coords) {
    const int b = blockIdx.x;
    const int w = threadIdx.x >> 5;
    const int l = threadIdx.x & 31;
    const int c4 = l * 4;                       // this thread's 4 channels (one head)
    const float4 q4 = *(const float4*)&g_q[(size_t)b * 128 + c4];
    const float rx = g_rbpos[b * 3 + 0];
    const float ry = g_rbpos[b * 3 + 1];
    const float rz = g_rbpos[b * 3 + 2];
    const int s0 = g_off[b], s1 = g_off[b + 1];
    const float INVSTEP = (float)(TABN - 1) / DMAX;

    float m = -1e30f, s = 0.f;
    float ax = 0.f, ay = 0.f, az = 0.f, aw = 0.f;

    for (int i = s0 + w; i < s1; i += 4) {
        int e = g_eidx[i];
        int src = edge_src[e];
        float dx = coords[(size_t)src * 3 + 0] - rx;
        float dy = coords[(size_t)src * 3 + 1] - ry;
        float dz = coords[(size_t)src * 3 + 2] - rz;
        float dist = sqrtf(dx * dx + dy * dy + dz * dz);
        float u = fminf(dist * INVSTEP, (float)(TABN - 1) - 1e-3f);
        int i0 = (int)u;
        float f = u - (float)i0;
        const float* t = &g_tab[(size_t)i0 * 256];
        float4 k0 = *(const float4*)&t[c4];
        float4 k1 = *(const float4*)&t[256 + c4];
        float4 v0 = *(const float4*)&t[128 + c4];
        float4 v1 = *(const float4*)&t[384 + c4];
        float4 ka = *(const float4*)&g_katom[(size_t)src * 128 + c4];
        float4 va = *(const float4*)&g_vatom[(size_t)src * 128 + c4];

        float kx = ka.x + k0.x + f * (k1.x - k0.x);
        float ky = ka.y + k0.y + f * (k1.y - k0.y);
        float kz = ka.z + k0.z + f * (k1.z - k0.z);
        float kw = ka.w + k0.w + f * (k1.w - k0.w);
        float vx = va.x + v0.x + f * (v1.x - v0.x);
        float vy = va.y + v0.y + f * (v1.y - v0.y);
        float vz = va.z + v0.z + f * (v1.z - v0.z);
        float vw = va.w + v0.w + f * (v1.w - v0.w);

        float part = q4.x * kx + q4.y * ky + q4.z * kz + q4.w * kw;
        part += __shfl_xor_sync(0xffffffffu, part, 1);   // reduce 4-lane head group
        part += __shfl_xor_sync(0xffffffffu, part, 2);
        float lg = part * 0.25f;                          // 1/sqrt(HEAD_DIM)

        float mn = fmaxf(m, lg);
        float sc = __expf(m - mn);
        float p = __expf(lg - mn);
        s = s * sc + p;
        ax = ax * sc + p * vx;
        ay = ay * sc + p * vy;
        az = az * sc + p * vz;
        aw = aw * sc + p * vw;
        m = mn;
    }

    __shared__ float msh[4][32], ssh[4][32];
    __shared__ float4 ash[4][32];
    msh[w][l] = m;
    ssh[w][l] = s;
    ash[w][l] = make_float4(ax, ay, az, aw);
    __syncthreads();
    if (w == 0) {
        float M = msh[0][l];
#pragma unroll
        for (int j = 1; j < 4; j++) M = fmaxf(M, msh[j][l]);
        float S = 0.f;
        float Ax = 0.f, Ay = 0.f, Az = 0.f, Aw = 0.f;
#pragma unroll
        for (int j = 0; j < 4; j++) {
            float e2 = __expf(msh[j][l] - M);
            S += ssh[j][l] * e2;
            float4 a = ash[j][l];
            Ax += a.x * e2; Ay += a.y * e2; Az += a.z * e2; Aw += a.w * e2;
        }
        float inv = 1.f / (S + 1e-16f);
        *(float4*)&g_msg[(size_t)b * 128 + c4] =
            make_float4(Ax * inv, Ay * inv, Az * inv, Aw * inv);
    }
}

// ------------------------- final tiny GEMM: y = h @ Wt2 + bt2 -------------
__global__ void t2_kernel(const float* __restrict__ Wt2, const float* __restrict__ bt2,
                          float* __restrict__ out) {
    int gt = blockIdx.x * blockDim.x + threadIdx.x;
    int warp = gt >> 5;
    int lane = gt & 31;
    if (warp >= NB) return;
    float a0 = 0.f, a1 = 0.f;
#pragma unroll
    for (int k = lane; k < 128; k += 32) {
        float h = g_h[(size_t)warp * 128 + k];
        a0 += h * Wt2[k * 2 + 0];
        a1 += h * Wt2[k * 2 + 1];
    }
#pragma unroll
    for (int o = 16; o; o >>= 1) {
        a0 += __shfl_xor_sync(0xffffffffu, a0, o);
        a1 += __shfl_xor_sync(0xffffffffu, a1, o);
    }
    if (lane == 0) {
        out[warp * 2 + 0] = a0 + bt2[0];
        out[warp * 2 + 1] = a1 + bt2[1];
    }
}

// ------------------------- launch -----------------------------------------
extern "C" void kernel_launch(void* const* d_in, const int* in_sizes, int n_in,
                              void* d_out, int out_size) {
    const float* atom_feats = (const float*)d_in[0];
    const float* coords     = (const float*)d_in[1];
    const int*   rbi        = (const int*)d_in[2];
    const int*   etgt       = (const int*)d_in[3];
    const int*   esrc       = (const int*)d_in[4];
    const int*   tt         = (const int*)d_in[5];
    const float* W_dih      = (const float*)d_in[6];
    const float* b_dih      = (const float*)d_in[7];
    const float* Wq         = (const float*)d_in[8];
    const float* bq         = (const float*)d_in[9];
    const float* Wk         = (const float*)d_in[10];
    const float* bk         = (const float*)d_in[11];
    const float* Wv         = (const float*)d_in[12];
    const float* bv         = (const float*)d_in[13];
    const float* Wout       = (const float*)d_in[14];
    const float* bout       = (const float*)d_in[15];
    const float* Wt1        = (const float*)d_in[16];
    const float* bt1        = (const float*)d_in[17];
    const float* Wt2        = (const float*)d_in[18];
    const float* bt2        = (const float*)d_in[19];
    float* out = (float*)d_out;

    float *pWab, *pWfq, *pbfq, *pWo1, *pbo1, *pS, *pQ, *pKat, *pVat, *pMsg, *pH;
    cudaGetSymbolAddress((void**)&pWab, g_Wab);
    cudaGetSymbolAddress((void**)&pWfq, g_Wfq);
    cudaGetSymbolAddress((void**)&pbfq, g_bfq);
    cudaGetSymbolAddress((void**)&pWo1, g_Wo1);
    cudaGetSymbolAddress((void**)&pbo1, g_bo1);
    cudaGetSymbolAddress((void**)&pS, g_S);
    cudaGetSymbolAddress((void**)&pQ, g_q);
    cudaGetSymbolAddress((void**)&pKat, g_katom);
    cudaGetSymbolAddress((void**)&pVat, g_vatom);
    cudaGetSymbolAddress((void**)&pMsg, g_msg);
    cudaGetSymbolAddress((void**)&pH, g_h);

    // prep
    prep_wab<<<(256 * 128 + 255) / 256, 256>>>(W_dih);
    prep_bias<<<1, 128>>>(b_dih, Wq, bq, bout, Wt1, bt1);
    build_table<<<TABN / 16, 128>>>(Wk, Wv);
    // weight-fusion GEMMs (tiny): Wfq = Wab@Wq ; Wo1 = Wout@Wt1
    gemm_kernel<128, false><<<4, 256>>>(pWab, Wq, bq, 0.0f, pWfq, 256);
    gemm_kernel<128, false><<<2, 256>>>(Wout, Wt1, bt1, 0.0f, pWo1, 128);

    // edge counting sort by target bond (deterministic after per-bond rank sort)
    zero_cnt<<<(NB + 255) / 256, 256>>>();
    hist_kernel<<<(NE + 255) / 256, 256>>>(etgt);
    scan_kernel<<<1, 1024>>>();
    scatter_kernel<<<(NE + 255) / 256, 256>>>(etgt);
    sort_lists<<<(NB + 7) / 8, 256>>>();

    // bond-side features -> q (single fused GEMM)
    gather_S<<<(NB * 128 + 255) / 256, 256>>>(atom_feats, tt);
    rbpos_kernel<<<(NB + 127) / 128, 128>>>(rbi, coords);
    gemm_kernel<256, false><<<(NB + 63) / 64, 256>>>(pS, pWfq, pbfq, 1.0f, pQ, NB);

    // atom-side k/v in one pass
    gemm_dual<<<(NATOMS + 63) / 64, 256>>>(atom_feats, Wk, bk, Wv, bv, pKat, pVat, NATOMS);

    // fused per-bond attention
    attn_kernel<<<NB, 128>>>(esrc, coords);

    // output MLP: h = gelu(msg@(Wout@Wt1) + fused bias), then y = h@Wt2 + bt2
    gemm_kernel<128, true><<<(NB + 63) / 64, 256>>>(pMsg, pWo1, pbo1, 1.0f, pH, NB);
    t2_kernel<<<(NB * 32 + 127) / 128, 128>>>(Wt2, bt2, out);

    (void)in_sizes; (void)n_in; (void)out_size;
}

// round 3
// speedup vs baseline: 1.3063x; 1.0817x over previous
#include <cuda_runtime.h>
#include <math.h>

// Problem constants (fixed shapes for this problem)
#define NATOMS 50000
#define NB     10000
#define NE     320000
#define MAXE   256
#define DD     32
#define DELTA  (5.0f / 31.0f)
#define GCOEFF (-0.5f / (DELTA * DELTA))

typedef unsigned long long ull;

// ------------------------- scratch (device globals; no allocs allowed) ----
__device__ float g_Wfq[256 * 128];            // (folded Wab) @ Wq
__device__ float g_bfq[128];
__device__ float g_Wo1[128 * 128];            // Wout @ Wt1
__device__ float g_bo1[128];
__device__ float g_S[NB * 256];               // [fi+fl | fj+fk]
__device__ float g_q[NB * 128];
__device__ float g_rbpos[NB * 3];
__device__ float g_katom[NATOMS * 128];
__device__ float g_vatom[NATOMS * 128];
__device__ float g_C[NB * 256];               // per-bond q·Wk_bot coefs [b][j][h]
__device__ float g_acc[NB * 128];             // attn value accumulator (pre-div)
__device__ float g_sjt[NB * 256];             // attn gaussian-basis accum [b][h][j]
__device__ float g_Ssum[NB * 8];              // softmax denominators per head
__device__ float g_msg[NB * 128];
__device__ float g_h[NB * 128];
__device__ int   g_cnt[NB];
__device__ int   g_off[NB + 1];
__device__ int   g_cur[NB];
__device__ int   g_eidx[NE];
__device__ int   g_src[NE];                   // sorted edge src atoms
__device__ float g_dist[NE];                  // sorted edge distances

// ------------------------- f32x2 packed-FMA helpers -----------------------
__device__ __forceinline__ ull pack2(float x, float y) {
    ull r;
    asm("mov.b64 %0, {%1, %2};" : "=l"(r) : "f"(x), "f"(y));
    return r;
}
__device__ __forceinline__ void unpack2(ull v, float& lo, float& hi) {
    asm("mov.b64 {%0, %1}, %2;" : "=f"(lo), "=f"(hi) : "l"(v));
}
__device__ __forceinline__ void fma2(ull& d, ull a, ull b) {
    asm("fma.rn.f32x2 %0, %1, %2, %0;" : "+l"(d) : "l"(a), "l"(b));
}

// ------------------------- fused setup kernel -----------------------------
// blocks [0,5000): gather_S ; [5000,5040): rbpos ; [5040,5080): zero_cnt ;
// block 5080: fused biases.
__global__ __launch_bounds__(256) void setup_kernel(const float* __restrict__ feats,
                                                    const int* __restrict__ tt,
                                                    const int* __restrict__ rbi,
                                                    const float* __restrict__ coords,
                                                    const float* __restrict__ b_dih,
                                                    const float* __restrict__ Wq,
                                                    const float* __restrict__ bq,
                                                    const float* __restrict__ bout,
                                                    const float* __restrict__ Wt1,
                                                    const float* __restrict__ bt1) {
    int bid = blockIdx.x;
    int tid = threadIdx.x;
    if (bid < 5000) {
        int idx = bid * 256 + tid;               // < NB*128
        int b = idx >> 7, c = idx & 127;
        int ai = tt[b * 4 + 0], aj = tt[b * 4 + 1], ak = tt[b * 4 + 2], al = tt[b * 4 + 3];
        g_S[(size_t)b * 256 + c]       = feats[(size_t)ai * 128 + c] + feats[(size_t)al * 128 + c];
        g_S[(size_t)b * 256 + 128 + c] = feats[(size_t)aj * 128 + c] + feats[(size_t)ak * 128 + c];
    } else if (bid < 5040) {
        int b = (bid - 5000) * 256 + tid;
        if (b < NB) {
            int a0 = rbi[b], a1 = rbi[NB + b];
#pragma unroll
            for (int i = 0; i < 3; i++)
                g_rbpos[b * 3 + i] = 0.5f * (coords[(size_t)a0 * 3 + i] + coords[(size_t)a1 * 3 + i]);
        }
    } else if (bid < 5080) {
        int b = (bid - 5040) * 256 + tid;
        if (b < NB) g_cnt[b] = 0;
    } else {
        if (tid < 128) {
            float s1 = 0.f, s2 = 0.f;
            for (int k = 0; k < 128; k++) {
                s1 += b_dih[k] * Wq[k * 128 + tid];
                s2 += bout[k] * Wt1[k * 128 + tid];
            }
            g_bfq[tid] = bq[tid] + 2.f * s1;
            g_bo1[tid] = bt1[tid] + s2;
        }
    }
}

// ------------------------- counting-sort pipeline -------------------------
__global__ void hist_kernel(const int* __restrict__ etgt) {
    int e = blockIdx.x * blockDim.x + threadIdx.x;
    if (e < NE) atomicAdd(&g_cnt[etgt[e]], 1);
}

__global__ __launch_bounds__(1024) void scan_kernel() {
    __shared__ int sm[1024];
    int t = threadIdx.x;
    const int CH = 10;
    int base = t * CH;
    int loc[CH];
    int tot = 0;
#pragma unroll
    for (int i = 0; i < CH; i++) {
        int v = (base + i < NB) ? g_cnt[base + i] : 0;
        loc[i] = tot;
        tot += v;
    }
    sm[t] = tot;
    __syncthreads();
    for (int off = 1; off < 1024; off <<= 1) {
        int v = (t >= off) ? sm[t - off] : 0;
        __syncthreads();
        sm[t] += v;
        __syncthreads();
    }
    int excl = sm[t] - tot;
#pragma unroll
    for (int i = 0; i < CH; i++) {
        if (base + i < NB) {
            int o = excl + loc[i];
            g_off[base + i] = o;
            g_cur[base + i] = o;
        }
    }
    if (t == 1023) g_off[NB] = sm[1023];
}

__global__ void scatter_kernel(const int* __restrict__ etgt) {
    int e = blockIdx.x * blockDim.x + threadIdx.x;
    if (e < NE) {
        int p = atomicAdd(&g_cur[etgt[e]], 1);
        g_eidx[p] = e;
    }
}

// sort each bond's edge list (determinism), then emit src + dist per slot.
__global__ __launch_bounds__(256) void sortify_kernel(const int* __restrict__ esrc,
                                                      const float* __restrict__ coords) {
    __shared__ int buf[8][MAXE];
    int warp = threadIdx.x >> 5, lane = threadIdx.x & 31;
    int b = blockIdx.x * 8 + warp;
    if (b >= NB) return;
    int s = g_off[b], e = g_off[b + 1];
    int n = e - s;
    if (n <= 0) return;
    if (n <= MAXE) {
        for (int i = lane; i < n; i += 32) buf[warp][i] = g_eidx[s + i];
        __syncwarp();
        for (int i = lane; i < n; i += 32) {
            int v = buf[warp][i];
            int r = 0;
            for (int j = 0; j < n; j++) r += (buf[warp][j] < v);
            g_eidx[s + r] = v;
        }
        __syncwarp();
    } else {
        if (lane == 0) {
            for (int i = s + 1; i < e; i++) {
                int key = g_eidx[i];
                int j = i - 1;
                while (j >= s && g_eidx[j] > key) { g_eidx[j + 1] = g_eidx[j]; j--; }
                g_eidx[j + 1] = key;
            }
        }
        __syncwarp();
    }
    float rx = g_rbpos[b * 3 + 0];
    float ry = g_rbpos[b * 3 + 1];
    float rz = g_rbpos[b * 3 + 2];
    for (int i = lane; i < n; i += 32) {
        int ed = g_eidx[s + i];
        int src = esrc[ed];
        g_src[s + i] = src;
        float dx = coords[(size_t)src * 3 + 0] - rx;
        float dy = coords[(size_t)src * 3 + 1] - ry;
        float dz = coords[(size_t)src * 3 + 2] - rz;
        g_dist[s + i] = sqrtf(dx * dx + dy * dy + dz * dz);
    }
}

// --------------- fused small weight GEMMs: Wfq (8 blocks) + Wo1 (4) -------
// 32-row tiles, 256 threads, 2x8 micro-tile. A for Wfq is the dihedral fold
// of W_dih computed in the loader; A for Wo1 is Wout.
__global__ __launch_bounds__(256) void gemm_weights(const float* __restrict__ Wd,
                                                    const float* __restrict__ Wq,
                                                    const float* __restrict__ Wout,
                                                    const float* __restrict__ Wt1) {
    __shared__ float As[32][33];
    __shared__ float Ws[32][128];
    const int tid = threadIdx.x;
    const int tx = tid & 15;
    const int ty = tid >> 4;
    const bool isFq = blockIdx.x < 8;
    const int m0 = isFq ? blockIdx.x * 32 : (blockIdx.x - 8) * 32;
    const float* W = isFq ? Wq : Wt1;
    float* C = isFq ? g_Wfq : g_Wo1;

    ull acc[2][4];
#pragma unroll
    for (int r = 0; r < 2; r++)
#pragma unroll
        for (int j = 0; j < 4; j++) acc[r][j] = 0ull;

    for (int kc = 0; kc < 128; kc += 32) {
        {
            int row = tid >> 3;
            int c4 = tid & 7;
            int gr = m0 + row;
            float4 v;
            if (isFq) {
                int o = (gr < 128) ? (gr + 384) : (gr + 128);
                float4 a = *(const float4*)(Wd + (size_t)gr * 128 + kc + c4 * 4);
                float4 b = *(const float4*)(Wd + (size_t)o * 128 + kc + c4 * 4);
                v = make_float4(a.x + b.x, a.y + b.y, a.z + b.z, a.w + b.w);
            } else {
                v = *(const float4*)(Wout + (size_t)gr * 128 + kc + c4 * 4);
            }
            As[c4 * 4 + 0][row] = v.x;
            As[c4 * 4 + 1][row] = v.y;
            As[c4 * 4 + 2][row] = v.z;
            As[c4 * 4 + 3][row] = v.w;
        }
#pragma unroll
        for (int it = 0; it < 4; it++) {
            int lin = tid + 256 * it;
            int row = lin >> 5;
            int c4 = lin & 31;
            *(float4*)&Ws[row][c4 * 4] =
                *(const float4*)(W + (size_t)(kc + row) * 128 + c4 * 4);
        }
        __syncthreads();
#pragma unroll
        for (int k = 0; k < 32; k++) {
            float a0 = As[k][ty * 2 + 0], a1 = As[k][ty * 2 + 1];
            ull pa0 = pack2(a0, a0), pa1 = pack2(a1, a1);
            const ull* wp = (const ull*)&Ws[k][tx * 8];
            ull w0 = wp[0], w1 = wp[1], w2 = wp[2], w3 = wp[3];
            fma2(acc[0][0], pa0, w0); fma2(acc[0][1], pa0, w1);
            fma2(acc[0][2], pa0, w2); fma2(acc[0][3], pa0, w3);
            fma2(acc[1][0], pa1, w0); fma2(acc[1][1], pa1, w1);
            fma2(acc[1][2], pa1, w2); fma2(acc[1][3], pa1, w3);
        }
        __syncthreads();
    }
#pragma unroll
    for (int r = 0; r < 2; r++) {
        int gr = m0 + ty * 2 + r;
#pragma unroll
        for (int j = 0; j < 4; j++) {
            float lo, hi;
            unpack2(acc[r][j], lo, hi);
            *(float2*)(C + (size_t)gr * 128 + tx * 8 + j * 2) = make_float2(lo, hi);
        }
    }
}

// ---------------- big GEMM launch: dual k/v (blocks < DUALB) + q ----------
#define DUALB 782
#define QB    157

__global__ __launch_bounds__(256) void gemm_big(const float* __restrict__ atom_feats,
                                                const float* __restrict__ Wk,
                                                const float* __restrict__ bk,
                                                const float* __restrict__ Wv,
                                                const float* __restrict__ bv) {
    __shared__ float As[32][65];
    __shared__ float Ws[2][32][128];
    const int tid = threadIdx.x;
    const int tx = tid & 15;
    const int ty = tid >> 4;

    if (blockIdx.x < DUALB) {
        const int m0 = blockIdx.x * 64;
        ull acc[2][4][4];
#pragma unroll
        for (int p = 0; p < 2; p++)
#pragma unroll
            for (int r = 0; r < 4; r++)
#pragma unroll
                for (int j = 0; j < 4; j++) acc[p][r][j] = 0ull;

        for (int kc = 0; kc < 128; kc += 32) {
#pragma unroll
            for (int it = 0; it < 2; it++) {
                int lin = tid + 256 * it;
                int row = lin >> 3;
                int c4 = lin & 7;
                float4 v = make_float4(0.f, 0.f, 0.f, 0.f);
                int gr = m0 + row;
                if (gr < NATOMS) v = *(const float4*)(atom_feats + (size_t)gr * 128 + kc + c4 * 4);
                As[c4 * 4 + 0][row] = v.x;
                As[c4 * 4 + 1][row] = v.y;
                As[c4 * 4 + 2][row] = v.z;
                As[c4 * 4 + 3][row] = v.w;
            }
#pragma unroll
            for (int it = 0; it < 4; it++) {
                int lin = tid + 256 * it;
                int row = lin >> 5;
                int c4 = lin & 31;
                *(float4*)&Ws[0][row][c4 * 4] =
                    *(const float4*)(Wk + (size_t)(kc + row) * 128 + c4 * 4);
                *(float4*)&Ws[1][row][c4 * 4] =
                    *(const float4*)(Wv + (size_t)(kc + row) * 128 + c4 * 4);
            }
            __syncthreads();
#pragma unroll
            for (int k = 0; k < 32; k++) {
                float a0 = As[k][ty * 4 + 0], a1 = As[k][ty * 4 + 1];
                float a2 = As[k][ty * 4 + 2], a3 = As[k][ty * 4 + 3];
                ull pa0 = pack2(a0, a0), pa1 = pack2(a1, a1);
                ull pa2 = pack2(a2, a2), pa3 = pack2(a3, a3);
#pragma unroll
                for (int p = 0; p < 2; p++) {
                    const ull* wp = (const ull*)&Ws[p][k][tx * 8];
                    ull w0 = wp[0], w1 = wp[1], w2 = wp[2], w3 = wp[3];
                    fma2(acc[p][0][0], pa0, w0); fma2(acc[p][0][1], pa0, w1);
                    fma2(acc[p][0][2], pa0, w2); fma2(acc[p][0][3], pa0, w3);
                    fma2(acc[p][1][0], pa1, w0); fma2(acc[p][1][1], pa1, w1);
                    fma2(acc[p][1][2], pa1, w2); fma2(acc[p][1][3], pa1, w3);
                    fma2(acc[p][2][0], pa2, w0); fma2(acc[p][2][1], pa2, w1);
                    fma2(acc[p][2][2], pa2, w2); fma2(acc[p][2][3], pa2, w3);
                    fma2(acc[p][3][0], pa3, w0); fma2(acc[p][3][1], pa3, w1);
                    fma2(acc[p][3][2], pa3, w2); fma2(acc[p][3][3], pa3, w3);
                }
            }
            __syncthreads();
        }
#pragma unroll
        for (int p = 0; p < 2; p++) {
            const float* bias = p ? bv : bk;
            float* C = p ? g_vatom : g_katom;
            float bb[8];
#pragma unroll
            for (int j = 0; j < 8; j++) bb[j] = bias[tx * 8 + j];
#pragma unroll
            for (int r = 0; r < 4; r++) {
                int gr = m0 + ty * 4 + r;
                if (gr >= NATOMS) continue;
#pragma unroll
                for (int j = 0; j < 4; j++) {
                    float lo, hi;
                    unpack2(acc[p][r][j], lo, hi);
                    *(float2*)(C + (size_t)gr * 128 + tx * 8 + j * 2) =
                        make_float2(lo + bb[j * 2], hi + bb[j * 2 + 1]);
                }
            }
        }
    } else {
        // q = S @ Wfq + bfq   (K = 256)
        const int m0 = (blockIdx.x - DUALB) * 64;
        ull acc[4][4];
#pragma unroll
        for (int r = 0; r < 4; r++)
#pragma unroll
            for (int j = 0; j < 4; j++) acc[r][j] = 0ull;

        for (int kc = 0; kc < 256; kc += 32) {
#pragma unroll
            for (int it = 0; it < 2; it++) {
                int lin = tid + 256 * it;
                int row = lin >> 3;
                int c4 = lin & 7;
                float4 v = make_float4(0.f, 0.f, 0.f, 0.f);
                int gr = m0 + row;
                if (gr < NB) v = *(const float4*)(g_S + (size_t)gr * 256 + kc + c4 * 4);
                As[c4 * 4 + 0][row] = v.x;
                As[c4 * 4 + 1][row] = v.y;
                As[c4 * 4 + 2][row] = v.z;
                As[c4 * 4 + 3][row] = v.w;
            }
#pragma unroll
            for (int it = 0; it < 4; it++) {
                int lin = tid + 256 * it;
                int row = lin >> 5;
                int c4 = lin & 31;
                *(float4*)&Ws[0][row][c4 * 4] =
                    *(const float4*)(g_Wfq + (size_t)(kc + row) * 128 + c4 * 4);
            }
            __syncthreads();
#pragma unroll
            for (int k = 0; k < 32; k++) {
                float a0 = As[k][ty * 4 + 0], a1 = As[k][ty * 4 + 1];
                float a2 = As[k][ty * 4 + 2], a3 = As[k][ty * 4 + 3];
                ull pa0 = pack2(a0, a0), pa1 = pack2(a1, a1);
                ull pa2 = pack2(a2, a2), pa3 = pack2(a3, a3);
                const ull* wp = (const ull*)&Ws[0][k][tx * 8];
                ull w0 = wp[0], w1 = wp[1], w2 = wp[2], w3 = wp[3];
                fma2(acc[0][0], pa0, w0); fma2(acc[0][1], pa0, w1);
                fma2(acc[0][2], pa0, w2); fma2(acc[0][3], pa0, w3);
                fma2(acc[1][0], pa1, w0); fma2(acc[1][1], pa1, w1);
                fma2(acc[1][2], pa1, w2); fma2(acc[1][3], pa1, w3);
                fma2(acc[2][0], pa2, w0); fma2(acc[2][1], pa2, w1);
                fma2(acc[2][2], pa2, w2); fma2(acc[2][3], pa2, w3);
                fma2(acc[3][0], pa3, w0); fma2(acc[3][1], pa3, w1);
                fma2(acc[3][2], pa3, w2); fma2(acc[3][3], pa3, w3);
            }
            __syncthreads();
        }
        float bb[8];
#pragma unroll
        for (int j = 0; j < 8; j++) bb[j] = g_bfq[tx * 8 + j];
#pragma unroll
        for (int r = 0; r < 4; r++) {
            int gr = m0 + ty * 4 + r;
            if (gr >= NB) continue;
#pragma unroll
            for (int j = 0; j < 4; j++) {
                float lo, hi;
                unpack2(acc[r][j], lo, hi);
                *(float2*)(g_q + (size_t)gr * 128 + tx * 8 + j * 2) =
                    make_float2(lo + bb[j * 2], hi + bb[j * 2 + 1]);
            }
        }
    }
}

// --------- per-bond gaussian-basis logit coefs: C[b][j][h] ----------------
// warp per bond; Wk_bot (rows 128..159 of Wk) staged in smem per block.
__global__ __launch_bounds__(256) void qkcoef_kernel(const float* __restrict__ Wk) {
    __shared__ float wkbs[32][128];
    int tid = threadIdx.x;
    for (int idx = tid; idx < 32 * 128; idx += 256) {
        int j = idx >> 7, c = idx & 127;
        wkbs[j][c] = Wk[(size_t)(128 + j) * 128 + c];
    }
    __syncthreads();
    int w = tid >> 5, l = tid & 31;
    int b = blockIdx.x * 8 + w;
    if (b >= NB) return;
    float4 q4 = *(const float4*)&g_q[(size_t)b * 128 + l * 4];
    int h = l >> 2;
#pragma unroll
    for (int j = 0; j < 32; j++) {
        float4 w4 = *(const float4*)&wkbs[j][l * 4];
        float part = q4.x * w4.x + q4.y * w4.y + q4.z * w4.z + q4.w * w4.w;
        part += __shfl_xor_sync(0xffffffffu, part, 1);
        part += __shfl_xor_sync(0xffffffffu, part, 2);
        if ((l & 3) == 0) g_C[(size_t)b * 256 + j * 8 + h] = part;
    }
}

// ------------------------- attention core ---------------------------------
// block per bond, 4 warps split edges; gaussian basis evaluated exactly.
__global__ __launch_bounds__(128) void attn_kernel() {
    __shared__ float Cs[32][8];
    __shared__ float msm[4][8], ssm[4][8];
    __shared__ float accs[4][128];
    __shared__ float sjs[4][256];
    __shared__ float fs[4][8];
    __shared__ float Ssm[8];

    const int b = blockIdx.x;
    const int tid = threadIdx.x;
    const int w = tid >> 5;
    const int l = tid & 31;
    const int h = l >> 2;
    const int t = l & 3;

    Cs[0][tid & 255] = 0.f;   // placate compiler; real load below
    // load C coefficients (256 floats)
    ((float*)Cs)[tid] = g_C[(size_t)b * 256 + tid];
    ((float*)Cs)[tid + 128] = g_C[(size_t)b * 256 + tid + 128];
    __syncthreads();

    const float4 q4 = *(const float4*)&g_q[(size_t)b * 128 + l * 4];
    const int s0 = g_off[b], s1 = g_off[b + 1];

    float m = -1e30f, s = 0.f;
    float ax = 0.f, ay = 0.f, az = 0.f, aw = 0.f;
    float sj[8];
#pragma unroll
    for (int jj = 0; jj < 8; jj++) sj[jj] = 0.f;

    int i = s0 + w;
    int src = 0; float dist = 0.f;
    if (i < s1) { src = g_src[i]; dist = g_dist[i]; }
    while (i < s1) {
        float4 ka = *(const float4*)&g_katom[(size_t)src * 128 + l * 4];
        float4 va = *(const float4*)&g_vatom[(size_t)src * 128 + l * 4];
        int ni = i + 4;
        int nsrc = 0; float ndist = 0.f;
        if (ni < s1) { nsrc = g_src[ni]; ndist = g_dist[ni]; }

        // gaussian basis for this lane's 8 j's (j = t + 4*jj)
        float ev[8];
        float epart = 0.f;
#pragma unroll
        for (int jj = 0; jj < 8; jj++) {
            int j = t + 4 * jj;
            float u = dist - (float)j * DELTA;
            float e = __expf(GCOEFF * u * u);
            ev[jj] = e;
            epart += e * Cs[j][h];
        }
        float part = q4.x * ka.x + q4.y * ka.y + q4.z * ka.z + q4.w * ka.w + epart;
        part += __shfl_xor_sync(0xffffffffu, part, 1);
        part += __shfl_xor_sync(0xffffffffu, part, 2);
        float lg = part * 0.25f;                   // 1/sqrt(HEAD_DIM)

        float mn = fmaxf(m, lg);
        float sc = __expf(m - mn);
        float p = __expf(lg - mn);
        s = s * sc + p;
        ax = ax * sc + p * va.x;
        ay = ay * sc + p * va.y;
        az = az * sc + p * va.z;
        aw = aw * sc + p * va.w;
#pragma unroll
        for (int jj = 0; jj < 8; jj++) sj[jj] = sj[jj] * sc + p * ev[jj];
        m = mn;

        i = ni; src = nsrc; dist = ndist;
    }

    if (t == 0) { msm[w][h] = m; ssm[w][h] = s; }
    accs[w][l * 4 + 0] = ax;
    accs[w][l * 4 + 1] = ay;
    accs[w][l * 4 + 2] = az;
    accs[w][l * 4 + 3] = aw;
#pragma unroll
    for (int jj = 0; jj < 8; jj++) sjs[w][l * 8 + jj] = sj[jj];
    __syncthreads();

    if (tid < 8) {
        float M = msm[0][tid];
#pragma unroll
        for (int ww = 1; ww < 4; ww++) M = fmaxf(M, msm[ww][tid]);
        float S = 0.f;
#pragma unroll
        for (int ww = 0; ww < 4; ww++) {
            float f = __expf(msm[ww][tid] - M);
            fs[ww][tid] = f;
            S += ssm[ww][tid] * f;
        }
        Ssm[tid] = S;
    }
    __syncthreads();

    {
        int hh = tid >> 4;
        float a = 0.f;
#pragma unroll
        for (int ww = 0; ww < 4; ww++) a += accs[ww][tid] * fs[ww][hh];
        g_acc[(size_t)b * 128 + tid] = a;
    }
#pragma unroll
    for (int r = 0; r < 2; r++) {
        int idx = tid + 128 * r;                 // [h][j] layout
        int hh = idx >> 5, j = idx & 31;
        int tt2 = j & 3, jj = j >> 2;
        float v = 0.f;
#pragma unroll
        for (int ww = 0; ww < 4; ww++) v += sjs[ww][(4 * hh + tt2) * 8 + jj] * fs[ww][hh];
        g_sjt[(size_t)b * 256 + idx] = v;
    }
    if (tid < 8) g_Ssum[b * 8 + tid] = Ssm[tid];
}

// ---------- value-basis correction + normalization: writes g_msg ----------
__global__ __launch_bounds__(256) void vcorr_kernel(const float* __restrict__ Wv) {
    __shared__ float Wvbs[128][33];
    __shared__ float sjsh[2][256];
    int tid = threadIdx.x;
    for (int idx = tid; idx < 32 * 128; idx += 256) {
        int j = idx >> 7, c = idx & 127;
        Wvbs[c][j] = Wv[(size_t)(128 + j) * 128 + c];
    }
    __syncthreads();
    int base = blockIdx.x * 16;
    int sub = tid >> 7;
    int c = tid & 127;
    int h = c >> 4;
    for (int it = 0; it < 8; it++) {
        int b0 = base + it * 2;
#pragma unroll
        for (int k = 0; k < 2; k++) {
            int lin = tid + 256 * k;
            int s2 = lin >> 8, off = lin & 255;
            sjsh[s2][off] = g_sjt[(size_t)(b0 + s2) * 256 + off];
        }
        __syncthreads();
        int b = b0 + sub;
        float acc = g_acc[(size_t)b * 128 + c];
        float S = g_Ssum[b * 8 + h];
        float corr = 0.f;
#pragma unroll
        for (int j = 0; j < 32; j++) corr += Wvbs[c][j] * sjsh[sub][h * 32 + j];
        g_msg[(size_t)b * 128 + c] = (acc + corr) / (S + 1e-16f);
        __syncthreads();
    }
}

// ------------------------- GELU GEMM: h = gelu(msg @ Wo1 + bo1) -----------
__global__ __launch_bounds__(256) void gemm_gelu() {
    __shared__ float As[32][65];
    __shared__ float Ws[32][128];
    const int tid = threadIdx.x;
    const int tx = tid & 15;
    const int ty = tid >> 4;
    const int m0 = blockIdx.x * 64;

    ull acc[4][4];
#pragma unroll
    for (int r = 0; r < 4; r++)
#pragma unroll
        for (int j = 0; j < 4; j++) acc[r][j] = 0ull;

    for (int kc = 0; kc < 128; kc += 32) {
#pragma unroll
        for (int it = 0; it < 2; it++) {
            int lin = tid + 256 * it;
            int row = lin >> 3;
            int c4 = lin & 7;
            float4 v = make_float4(0.f, 0.f, 0.f, 0.f);
            int gr = m0 + row;
            if (gr < NB) v = *(const float4*)(g_msg + (size_t)gr * 128 + kc + c4 * 4);
            As[c4 * 4 + 0][row] = v.x;
            As[c4 * 4 + 1][row] = v.y;
            As[c4 * 4 + 2][row] = v.z;
            As[c4 * 4 + 3][row] = v.w;
        }
#pragma unroll
        for (int it = 0; it < 4; it++) {
            int lin = tid + 256 * it;
            int row = lin >> 5;
            int c4 = lin & 31;
            *(float4*)&Ws[row][c4 * 4] =
                *(const float4*)(g_Wo1 + (size_t)(kc + row) * 128 + c4 * 4);
        }
        __syncthreads();
#pragma unroll
        for (int k = 0; k < 32; k++) {
            float a0 = As[k][ty * 4 + 0], a1 = As[k][ty * 4 + 1];
            float a2 = As[k][ty * 4 + 2], a3 = As[k][ty * 4 + 3];
            ull pa0 = pack2(a0, a0), pa1 = pack2(a1, a1);
            ull pa2 = pack2(a2, a2), pa3 = pack2(a3, a3);
            const ull* wp = (const ull*)&Ws[k][tx * 8];
            ull w0 = wp[0], w1 = wp[1], w2 = wp[2], w3 = wp[3];
            fma2(acc[0][0], pa0, w0); fma2(acc[0][1], pa0, w1);
            fma2(acc[0][2], pa0, w2); fma2(acc[0][3], pa0, w3);
            fma2(acc[1][0], pa1, w0); fma2(acc[1][1], pa1, w1);
            fma2(acc[1][2], pa1, w2); fma2(acc[1][3], pa1, w3);
            fma2(acc[2][0], pa2, w0); fma2(acc[2][1], pa2, w1);
            fma2(acc[2][2], pa2, w2); fma2(acc[2][3], pa2, w3);
            fma2(acc[3][0], pa3, w0); fma2(acc[3][1], pa3, w1);
            fma2(acc[3][2], pa3, w2); fma2(acc[3][3], pa3, w3);
        }
        __syncthreads();
    }

    float bb[8];
#pragma unroll
    for (int j = 0; j < 8; j++) bb[j] = g_bo1[tx * 8 + j];
#pragma unroll
    for (int r = 0; r < 4; r++) {
        int gr = m0 + ty * 4 + r;
        if (gr >= NB) continue;
#pragma unroll
        for (int j = 0; j < 4; j++) {
            float lo, hi;
            unpack2(acc[r][j], lo, hi);
            lo += bb[j * 2];
            hi += bb[j * 2 + 1];
            lo = 0.5f * lo * (1.f + erff(lo * 0.70710678118654752f));
            hi = 0.5f * hi * (1.f + erff(hi * 0.70710678118654752f));
            *(float2*)(g_h + (size_t)gr * 128 + tx * 8 + j * 2) = make_float2(lo, hi);
        }
    }
}

// ------------------------- final tiny GEMM: y = h @ Wt2 + bt2 -------------
__global__ void t2_kernel(const float* __restrict__ Wt2, const float* __restrict__ bt2,
                          float* __restrict__ out) {
    int gt = blockIdx.x * blockDim.x + threadIdx.x;
    int warp = gt >> 5;
    int lane = gt & 31;
    if (warp >= NB) return;
    float a0 = 0.f, a1 = 0.f;
#pragma unroll
    for (int k = lane; k < 128; k += 32) {
        float h = g_h[(size_t)warp * 128 + k];
        a0 += h * Wt2[k * 2 + 0];
        a1 += h * Wt2[k * 2 + 1];
    }
#pragma unroll
    for (int o = 16; o; o >>= 1) {
        a0 += __shfl_xor_sync(0xffffffffu, a0, o);
        a1 += __shfl_xor_sync(0xffffffffu, a1, o);
    }
    if (lane == 0) {
        out[warp * 2 + 0] = a0 + bt2[0];
        out[warp * 2 + 1] = a1 + bt2[1];
    }
}

// ------------------------- launch -----------------------------------------
extern "C" void kernel_launch(void* const* d_in, const int* in_sizes, int n_in,
                              void* d_out, int out_size) {
    const float* atom_feats = (const float*)d_in[0];
    const float* coords     = (const float*)d_in[1];
    const int*   rbi        = (const int*)d_in[2];
    const int*   etgt       = (const int*)d_in[3];
    const int*   esrc       = (const int*)d_in[4];
    const int*   tt         = (const int*)d_in[5];
    const float* W_dih      = (const float*)d_in[6];
    const float* b_dih      = (const float*)d_in[7];
    const float* Wq         = (const float*)d_in[8];
    const float* bq         = (const float*)d_in[9];
    const float* Wk         = (const float*)d_in[10];
    const float* bk         = (const float*)d_in[11];
    const float* Wv         = (const float*)d_in[12];
    const float* bv         = (const float*)d_in[13];
    const float* Wout       = (const float*)d_in[14];
    const float* bout       = (const float*)d_in[15];
    const float* Wt1        = (const float*)d_in[16];
    const float* bt1        = (const float*)d_in[17];
    const float* Wt2        = (const float*)d_in[18];
    const float* bt2        = (const float*)d_in[19];
    float* out = (float*)d_out;

    // 1. fused setup: gather_S, rbpos, zero_cnt, fused biases
    setup_kernel<<<5081, 256>>>(atom_feats, tt, rbi, coords,
                                b_dih, Wq, bq, bout, Wt1, bt1);
    // 2-5. counting sort + deterministic ordering + src/dist precompute
    hist_kernel<<<(NE + 255) / 256, 256>>>(etgt);
    scan_kernel<<<1, 1024>>>();
    scatter_kernel<<<(NE + 255) / 256, 256>>>(etgt);
    sortify_kernel<<<(NB + 7) / 8, 256>>>(esrc, coords);
    // 6. fused small weight GEMMs: Wfq (dihedral fold inline) + Wo1
    gemm_weights<<<12, 256>>>(W_dih, Wq, Wout, Wt1);
    // 7. big GEMMs in one launch: atom k/v (dual) + bond q
    gemm_big<<<DUALB + QB, 256>>>(atom_feats, Wk, bk, Wv, bv);
    // 8. per-bond gaussian logit coefficients
    qkcoef_kernel<<<(NB + 7) / 8, 256>>>(Wk);
    // 9. fused attention (flash-style, gaussian basis exact)
    attn_kernel<<<NB, 128>>>();
    // 10. value-basis correction + normalization -> msg
    vcorr_kernel<<<NB / 16, 256>>>(Wv);
    // 11. h = gelu(msg @ (Wout@Wt1) + fused bias)
    gemm_gelu<<<(NB + 63) / 64, 256>>>();
    // 12. y = h @ Wt2 + bt2
    t2_kernel<<<(NB * 32 + 127) / 128, 128>>>(Wt2, bt2, out);

    (void)in_sizes; (void)n_in; (void)out_size;
}